// round 17
// baseline (speedup 1.0000x reference)
#include <cuda_runtime.h>
#include <cuda_bf16.h>
#include <cstdint>

// BTT forward via mma.sync bf16 (HMMA, baseline PTX), 3-term hi/lo split as
// K-extension with dedup'd smem segments:  A segs {hi,lo,hi} x B segs {hi,hi,lo}.
// Weights pre-converted once into GEMM-ready bf16 images (w0e, w1e).
// Z kept as two bf16 planes (hi, lo), b-contiguous. ALL global stores are
// coalesced via smem-transpose epilogues (s1 and s2). s2 writes transposed
// g_O[(y*64+ii)][b]; tr_kernel emits out[b][col] + bias.

__device__ __nv_bfloat16 g_Zhi[(size_t)16384 * 8192];  // 256 MiB
__device__ __nv_bfloat16 g_Zlo[(size_t)16384 * 8192];  // 256 MiB
__device__ __nv_bfloat16 g_w0e[64 * 256 * 128];        // 4 MiB  [j][n][hi64|lo64]
__device__ __nv_bfloat16 g_w1e[64 * 64 * 512];         // 4 MiB  [ii][y][kc4][hi64|lo64]
__device__ float        g_O[(size_t)4096 * 8192];      // 128 MiB [(y*64+ii)][b]

// ---------------------------------------------------------------------------
__device__ __forceinline__ uint32_t smem_u32(const void* p) {
    return (uint32_t)__cvta_generic_to_shared(p);
}
__device__ __forceinline__ void ldsm_x4(uint32_t* r, uint32_t addr) {
    asm volatile("ldmatrix.sync.aligned.m8n8.x4.shared.b16 {%0,%1,%2,%3}, [%4];"
                 : "=r"(r[0]), "=r"(r[1]), "=r"(r[2]), "=r"(r[3]) : "r"(addr));
}
__device__ __forceinline__ void ldsm_x4_t(uint32_t* r, uint32_t addr) {
    asm volatile("ldmatrix.sync.aligned.m8n8.x4.trans.shared.b16 {%0,%1,%2,%3}, [%4];"
                 : "=r"(r[0]), "=r"(r[1]), "=r"(r[2]), "=r"(r[3]) : "r"(addr));
}
__device__ __forceinline__ void mma_bf16(float* c, const uint32_t* a, const uint32_t* b) {
    asm volatile("mma.sync.aligned.m16n8k16.row.col.f32.bf16.bf16.f32 "
                 "{%0,%1,%2,%3}, {%4,%5,%6,%7}, {%8,%9}, {%0,%1,%2,%3};"
                 : "+f"(c[0]), "+f"(c[1]), "+f"(c[2]), "+f"(c[3])
                 : "r"(a[0]), "r"(a[1]), "r"(a[2]), "r"(a[3]), "r"(b[0]), "r"(b[1]));
}
__device__ __forceinline__ void cp16(uint32_t dst, const void* src) {
    asm volatile("cp.async.cg.shared.global [%0], [%1], 16;" :: "r"(dst), "l"(src));
}
#define CP_COMMIT()  asm volatile("cp.async.commit_group;")
#define CP_WAIT(n)   asm volatile("cp.async.wait_group %0;" :: "n"(n))

__device__ __forceinline__ void split1(float v, __nv_bfloat16& h, __nv_bfloat16& l) {
    h = __float2bfloat16(v);
    l = __float2bfloat16(v - __bfloat162float(h));
}
__device__ __forceinline__ uint32_t pack_hilo(float v) {
    __nv_bfloat16 h, l;
    split1(v, h, l);
    return ((uint32_t)__bfloat16_as_ushort(h) << 16) | (uint32_t)__bfloat16_as_ushort(l);
}
__device__ __forceinline__ void split4(float4 v, uint2& hip, uint2& lop) {
    uint32_t p0 = pack_hilo(v.x), p1 = pack_hilo(v.y);
    uint32_t p2 = pack_hilo(v.z), p3 = pack_hilo(v.w);
    hip.x = (p0 >> 16) | (p1 & 0xFFFF0000u);
    hip.y = (p2 >> 16) | (p3 & 0xFFFF0000u);
    lop.x = (p0 & 0xFFFFu) | (p1 << 16);
    lop.y = (p2 & 0xFFFFu) | (p3 << 16);
}

// ---------------------------------------------------------------------------
// Prep kernels: one-time weight conversion (outputs L2-resident, 4 MiB each)
// ---------------------------------------------------------------------------
__global__ void prep0_kernel(const float* __restrict__ c0) {
    const int j = blockIdx.x, n = threadIdx.x;
    __nv_bfloat16* dst = g_w0e + ((size_t)j * 256 + n) * 128;
#pragma unroll 4
    for (int x = 0; x < 64; x++) {
        __nv_bfloat16 h, l;
        split1(c0[(size_t)j * 16384 + x * 256 + n], h, l);
        dst[x] = h;
        dst[64 + x] = l;
    }
}
__global__ void prep1_kernel(const float* __restrict__ c1) {
    const int xp = blockIdx.x, t = threadIdx.x;
    const int ii = t >> 2, a = t & 3;
    const int kc = xp >> 4, kl = (xp & 15) * 4 + a;
#pragma unroll 4
    for (int y = 0; y < 64; y++) {
        __nv_bfloat16 h, l;
        split1(c1[(size_t)xp * 16384 + y * 256 + t], h, l);
        __nv_bfloat16* dst = g_w1e + ((size_t)ii * 64 + y) * 512 + kc * 128;
        dst[kl] = h;
        dst[64 + kl] = l;
    }
}

// ---------------------------------------------------------------------------
// Stage 1: tile M=128(b) x N=128(n), Kext=192 via dedup'd [hi|lo] segments.
// 8 warps (2m x 4n), warp tile 64x32.
// smem: A[m 128][hi64|lo64 hw] stride 272; B[n 128][hi64|lo64 hw] stride 272.
// Epilogue reuses smem as two [n 128][m 128] bf16 planes (272B stride, XOR-
// swizzled 16B chunks), then coalesced row stores to g_Zhi/g_Zlo.
// ---------------------------------------------------------------------------
#define S1_STRIDE 272
#define S1_B_OFF  34816
#define S1_SMEM   69632

__global__ void __launch_bounds__(256, 2) s1_kernel(const float* __restrict__ x) {
    extern __shared__ char sm[];
    char* smA = sm;
    const uint32_t sbA = smem_u32(sm), sbB = sbA + S1_B_OFF;

    const int tid = threadIdx.x, wid = tid >> 5, lane = tid & 31;
    const int col0 = blockIdx.x * 128;
    const int row0 = blockIdx.y * 128;
    const int j    = blockIdx.z;

    // --- B: cp.async from w0e, rows n = col0..col0+127, 256B each ---
    {
        const int r = tid >> 1, c0b = (tid & 1) * 8;
        const char* src = reinterpret_cast<const char*>(
            g_w0e + ((size_t)j * 256 + col0 + r) * 128);
        const uint32_t dst = sbB + r * S1_STRIDE;
#pragma unroll
        for (int q = 0; q < 8; q++)
            cp16(dst + (c0b + q) * 16, src + (c0b + q) * 16);
        CP_COMMIT();
    }
    // --- A: X[128 b][64 k] -> [m][hi(64)|lo(64)] (overlaps cp.async B) ---
    {
        const int m = tid >> 1, kh = tid & 1;
        const float* src = x + (size_t)(row0 + m) * 4096 + j * 64 + kh * 32;
        char* dst = smA + m * S1_STRIDE;
#pragma unroll
        for (int q = 0; q < 8; q++) {
            float4 v = *reinterpret_cast<const float4*>(src + q * 4);
            uint2 hp, lp;
            split4(v, hp, lp);
            const int k = kh * 32 + q * 4;
            *reinterpret_cast<uint2*>(dst + k * 2)        = hp;
            *reinterpret_cast<uint2*>(dst + (64 + k) * 2) = lp;
        }
    }
    CP_WAIT(0);
    __syncthreads();

    const int mw = (wid & 1) * 64;
    const int nw = (wid >> 1) * 32;

    float acc[4][4][4];
#pragma unroll
    for (int mi = 0; mi < 4; mi++)
#pragma unroll
        for (int ni = 0; ni < 4; ni++)
#pragma unroll
            for (int r = 0; r < 4; r++) acc[mi][ni][r] = 0.f;

    uint32_t aAddr[4], bAddr[2];
#pragma unroll
    for (int mi = 0; mi < 4; mi++)
        aAddr[mi] = sbA + (mw + mi * 16 + (lane & 15)) * S1_STRIDE + ((lane >> 4) * 8) * 2;
#pragma unroll
    for (int nj = 0; nj < 2; nj++)
        bAddr[nj] = sbB + (nw + nj * 16 + ((lane >> 4) << 3) + (lane & 7)) * S1_STRIDE
                        + (((lane >> 3) & 1) * 8) * 2;

    // s: A seg {hi,lo,hi}, B seg {hi,hi,lo}; q: k16 within 64
#pragma unroll 2
    for (int ks = 0; ks < 12; ks++) {
        const int s = ks >> 2, q = ks & 3;
        const int aoff = ((s == 1 ? 64 : 0) + q * 16) * 2;
        const int boff = ((s == 2 ? 64 : 0) + q * 16) * 2;
        uint32_t af[4][4], bf[2][4];
#pragma unroll
        for (int mi = 0; mi < 4; mi++) ldsm_x4(af[mi], aAddr[mi] + aoff);
#pragma unroll
        for (int nj = 0; nj < 2; nj++) ldsm_x4(bf[nj], bAddr[nj] + boff);
#pragma unroll
        for (int mi = 0; mi < 4; mi++)
#pragma unroll
            for (int nj = 0; nj < 2; nj++) {
                mma_bf16(acc[mi][nj * 2],     af[mi], &bf[nj][0]);
                mma_bf16(acc[mi][nj * 2 + 1], af[mi], &bf[nj][2]);
            }
    }

    // --- epilogue: smem transpose [n][m] (swizzled), then coalesced stores ---
    __syncthreads();  // done reading A/B smem; reuse it
    char* pH = sm;            // 128 rows x 272B
    char* pL = sm + 34816;
#pragma unroll
    for (int mi = 0; mi < 4; mi++)
#pragma unroll
        for (int ni = 0; ni < 4; ni++)
#pragma unroll
            for (int r = 0; r < 4; r++) {
                const int m = mw + mi * 16 + (lane >> 2) + (r >> 1) * 8;
                const int n = nw + ni * 8 + (lane & 3) * 2 + (r & 1);
                __nv_bfloat16 h, l;
                split1(acc[mi][ni][r], h, l);
                const uint32_t off =
                    n * S1_STRIDE + ((((m >> 3) ^ (n & 7)) << 4) | ((m * 2) & 15));
                *reinterpret_cast<__nv_bfloat16*>(pH + off) = h;
                *reinterpret_cast<__nv_bfloat16*>(pL + off) = l;
            }
    __syncthreads();
    {
        const int r = tid >> 1, hh = tid & 1;  // r = local n, hh = m-half
        const int nglob = col0 + r;
        const size_t zrow = (size_t)(nglob >> 2) * 256 + j * 4 + (nglob & 3);
        __nv_bfloat16* dH = g_Zhi + zrow * 8192 + row0 + hh * 64;
        __nv_bfloat16* dL = g_Zlo + zrow * 8192 + row0 + hh * 64;
#pragma unroll
        for (int q = 0; q < 8; q++) {
            const int lchunk = hh * 8 + q;
            const int pc = lchunk ^ (r & 7);
            *reinterpret_cast<uint4*>(dH + q * 8) =
                *reinterpret_cast<const uint4*>(pH + r * S1_STRIDE + pc * 16);
            *reinterpret_cast<uint4*>(dL + q * 8) =
                *reinterpret_cast<const uint4*>(pL + r * S1_STRIDE + pc * 16);
        }
    }
}

// ---------------------------------------------------------------------------
// Stage 2: tile M=128(b) x N=64(y), K=256 in 4 chunks of 64 (192 ext each).
// 8 warps (4m x 2n), warp tile 32b x 32y. All operands via cp.async, double-
// buffered. Epilogue: smem transpose [y][m] f32 (swizzled) -> coalesced g_O.
// ---------------------------------------------------------------------------
#define S2_STRIDE 272
#define S2_ASEG   17408              /* 64 * 272 */
#define S2_ABUF   (2 * S2_ASEG)      /* hi + lo */
#define S2_B_OFF  (2 * S2_ABUF)      /* 69632 */
#define S2_BBUF   17408
#define S2_SMEM   (S2_B_OFF + 2 * S2_BBUF) /* 104448 */
#define S2_OSTRIDE 528               /* 128 f32 + 16B pad */

__global__ void __launch_bounds__(256, 2) s2_kernel() {
    extern __shared__ char sm[];
    const uint32_t sbA = smem_u32(sm), sbB = sbA + S2_B_OFF;

    const int tid = threadIdx.x, wid = tid >> 5, lane = tid & 31;
    const int ii   = blockIdx.x;
    const int row0 = blockIdx.y * 128;

    const int mw = (wid & 3) * 32;   // warp b tile (32 b)
    const int nw = (wid >> 2) * 32;  // warp y tile

    const int lr = tid >> 2, lc = tid & 3;

    auto loadChunk = [&](int kc, int buf) {
        const size_t arow = (size_t)(ii * 256 + kc * 64 + lr) * 8192 + row0;
        const uint32_t adst = sbA + buf * S2_ABUF + lr * S2_STRIDE;
#pragma unroll
        for (int q = 0; q < 4; q++)
            cp16(adst + (lc + q * 4) * 16,
                 reinterpret_cast<const char*>(g_Zhi + arow) + (lc + q * 4) * 16);
#pragma unroll
        for (int q = 0; q < 4; q++)
            cp16(adst + S2_ASEG + (lc + q * 4) * 16,
                 reinterpret_cast<const char*>(g_Zlo + arow) + (lc + q * 4) * 16);
        const char* bsrc = reinterpret_cast<const char*>(
            g_w1e + ((size_t)ii * 64 + lr) * 512 + kc * 128);
        const uint32_t bdst = sbB + buf * S2_BBUF + lr * S2_STRIDE;
#pragma unroll
        for (int q = 0; q < 4; q++)
            cp16(bdst + (lc + q * 4) * 16, bsrc + (lc + q * 4) * 16);
        CP_COMMIT();
    };

    float acc[2][4][4];
#pragma unroll
    for (int mi = 0; mi < 2; mi++)
#pragma unroll
        for (int n8 = 0; n8 < 4; n8++)
#pragma unroll
            for (int r = 0; r < 4; r++) acc[mi][n8][r] = 0.f;

    uint32_t aAddr[2], bAddr[2];
#pragma unroll
    for (int mi = 0; mi < 2; mi++)  // A is [k][b]: trans ldmatrix
        aAddr[mi] = sbA + (lane & 15) * S2_STRIDE + (mw + mi * 16 + (lane >> 4) * 8) * 2;
#pragma unroll
    for (int nj = 0; nj < 2; nj++)
        bAddr[nj] = sbB + (nw + nj * 16 + ((lane >> 4) << 3) + (lane & 7)) * S2_STRIDE
                        + (((lane >> 3) & 1) * 8) * 2;

    loadChunk(0, 0);

#pragma unroll 1
    for (int kc = 0; kc < 4; kc++) {
        const int buf = kc & 1;
        if (kc < 3) loadChunk(kc + 1, buf ^ 1);
        if (kc < 3) { CP_WAIT(1); } else { CP_WAIT(0); }
        __syncthreads();

        const uint32_t aBase = buf * S2_ABUF;
        const uint32_t bBase = buf * S2_BBUF;
#pragma unroll
        for (int s = 0; s < 3; s++) {
            const uint32_t aSeg = aBase + (s == 1 ? S2_ASEG : 0);
            const int boff = (s == 2 ? 64 : 0) * 2;
#pragma unroll
            for (int q = 0; q < 4; q++) {
                uint32_t t[2][4], bf[2][4];
#pragma unroll
                for (int mi = 0; mi < 2; mi++)
                    ldsm_x4_t(t[mi], aAddr[mi] + aSeg + q * 16 * S2_STRIDE);
#pragma unroll
                for (int nj = 0; nj < 2; nj++)
                    ldsm_x4(bf[nj], bAddr[nj] + bBase + boff + q * 32);
#pragma unroll
                for (int mi = 0; mi < 2; mi++) {
                    uint32_t af[4] = {t[mi][0], t[mi][2], t[mi][1], t[mi][3]};
#pragma unroll
                    for (int nj = 0; nj < 2; nj++) {
                        mma_bf16(acc[mi][nj * 2],     af, &bf[nj][0]);
                        mma_bf16(acc[mi][nj * 2 + 1], af, &bf[nj][2]);
                    }
                }
            }
        }
        __syncthreads();
    }

    // --- epilogue: smem transpose [y][m] f32 (swizzled), coalesced g_O ---
    char* pO = sm;  // 64 rows x 528B = 33792 B (fits in S2_SMEM)
#pragma unroll
    for (int mi = 0; mi < 2; mi++)
#pragma unroll
        for (int n8 = 0; n8 < 4; n8++)
#pragma unroll
            for (int r = 0; r < 4; r++) {
                const int m = mw + mi * 16 + (lane >> 2) + (r >> 1) * 8;
                const int y = nw + n8 * 8 + (lane & 3) * 2 + (r & 1);
                const uint32_t off =
                    y * S2_OSTRIDE + ((((m >> 2) ^ (y & 7)) << 4) | ((m & 3) * 4));
                *reinterpret_cast<float*>(pO + off) = acc[mi][n8][r];
            }
    __syncthreads();
    {
        const int y = tid >> 2, c = tid & 3;
        float* dst = g_O + (size_t)(y * 64 + ii) * 8192 + row0;
#pragma unroll
        for (int q = 0; q < 8; q++) {
            const int lchunk = c * 8 + q;
            const int pc = lchunk ^ (y & 7);
            *reinterpret_cast<uint4*>(dst + lchunk * 4) =
                *reinterpret_cast<const uint4*>(pO + y * S2_OSTRIDE + pc * 16);
        }
    }
}

// ---------------------------------------------------------------------------
// Final transpose: out[b][col] = g_O[col][b] + bias[col]. 32x32 smem tiles.
// ---------------------------------------------------------------------------
__global__ void __launch_bounds__(256) tr_kernel(const float* __restrict__ bias,
                                                 float* __restrict__ out) {
    __shared__ float t[32][33];
    const int b0 = blockIdx.x * 32, c0 = blockIdx.y * 32;
    const int tx = threadIdx.x & 31, ty = threadIdx.x >> 5;  // 32 x 8
#pragma unroll
    for (int i = 0; i < 4; i++)
        t[ty + i * 8][tx] = g_O[(size_t)(c0 + ty + i * 8) * 8192 + b0 + tx];
    __syncthreads();
#pragma unroll
    for (int i = 0; i < 4; i++)
        out[(size_t)(b0 + ty + i * 8) * 4096 + c0 + tx] = t[tx][ty + i * 8] + bias[c0 + tx];
}

extern "C" void kernel_launch(void* const* d_in, const int* in_sizes, int n_in,
                              void* d_out, int out_size) {
    const float* x    = (const float*)d_in[0];  // (8192, 4096)
    const float* c0   = (const float*)d_in[1];  // (64,64,64,4,1)
    const float* c1   = (const float*)d_in[2];  // (64,64,64,1,4)
    const float* bias = (const float*)d_in[3];  // (4096,)
    float* out = (float*)d_out;                 // (8192, 4096)

    cudaFuncSetAttribute(s1_kernel, cudaFuncAttributeMaxDynamicSharedMemorySize, S1_SMEM);
    cudaFuncSetAttribute(s2_kernel, cudaFuncAttributeMaxDynamicSharedMemorySize, S2_SMEM);

    prep0_kernel<<<64, 256>>>(c0);
    prep1_kernel<<<64, 256>>>(c1);
    s1_kernel<<<dim3(2, 64, 64), 256, S1_SMEM>>>(x);      // (ntile, mtile, j)
    s2_kernel<<<dim3(64, 64), 256, S2_SMEM>>>();          // (ii, mtile)
    tr_kernel<<<dim3(256, 128), 256>>>(bias, out);
}